// round 12
// baseline (speedup 1.0000x reference)
#include <cuda_runtime.h>
#include <cuda_bf16.h>
#include <cstdint>

#define N_ATOMS 50000
#define M_NBR   32
#define NE      (N_ATOMS * M_NBR)   // 1,600,000 edges
#define NBR_F   64
#define ATOM_F  128
#define SH_DIM  9
#define INV_SQRT_F 0.08838834764831845f

#define TILE_E        128            // edges per tile (8 warps x 16 edges)
#define TILES_PER_CTA 8
#define N_TILES_TOTAL (NE / TILE_E)              // 12500
#define N_EDGE_CTAS   ((N_TILES_TOTAL + TILES_PER_CTA - 1) / TILES_PER_CTA)  // 1563

// ---- edge-kernel smem layout (byte offsets from 1024-aligned base) ----
#define OFF_A_HI   0                 // 128 x 64 bf16, swizzled 128B rows (16384)
#define OFF_A_LO   16384             // 16384
#define OFF_B_HI   32768             // 64 x 64 bf16 row-major [k][j], swz (8192)
#define OFF_B_LO   40960             // 8192
#define OFF_BW     49152             // 32 x float4 {b1[2j],b1[2j+1],w2[2j],w2[2j+1]}
#define OFF_RAW    49664             // 128 x 64 f32 raw tile (32768)
#define EDGE_SMEM_USED 82432
#define EDGE_SMEM_BYTES (EDGE_SMEM_USED + 1024)

__device__ float g_S[N_ATOMS];
__device__ float g_C[N_ATOMS];

__global__ void zero_kernel() {
    int i = blockIdx.x * blockDim.x + threadIdx.x;
    if (i < N_ATOMS) { g_S[i] = 0.0f; g_C[i] = 0.0f; }
}

// ======================= helpers =======================
__device__ __forceinline__ uint32_t smem_u32(const void* p) {
    uint32_t a;
    asm("{ .reg .u64 t; cvta.to.shared.u64 t, %1; cvt.u32.u64 %0, t; }"
        : "=r"(a) : "l"(p));
    return a;
}
__device__ __forceinline__ void sts64(uint32_t addr, unsigned long long v) {
    asm volatile("st.shared.b64 [%0], %1;" :: "r"(addr), "l"(v) : "memory");
}
__device__ __forceinline__ void sts16(uint32_t addr, unsigned short v) {
    asm volatile("st.shared.b16 [%0], %1;" :: "r"(addr), "h"(v) : "memory");
}
#define SMEM_SWZ(off) ((off) ^ (((off) >> 3) & 0x70))

__device__ __forceinline__ void ldsm_x4(uint32_t addr, uint32_t* r) {
    asm volatile("ldmatrix.sync.aligned.m8n8.x4.shared.b16 {%0,%1,%2,%3}, [%4];"
        : "=r"(r[0]), "=r"(r[1]), "=r"(r[2]), "=r"(r[3]) : "r"(addr));
}
// x4 trans: loads TWO n-tiles' B fragments (lanes 0-15 -> nt, 16-31 -> nt+1)
__device__ __forceinline__ void ldsm_x4t(uint32_t addr, uint32_t* r) {
    asm volatile("ldmatrix.sync.aligned.m8n8.x4.trans.shared.b16 {%0,%1,%2,%3}, [%4];"
        : "=r"(r[0]), "=r"(r[1]), "=r"(r[2]), "=r"(r[3]) : "r"(addr));
}
__device__ __forceinline__ void mma_bf16(float* d, const uint32_t* a,
                                         uint32_t b0, uint32_t b1) {
    asm volatile("mma.sync.aligned.m16n8k16.row.col.f32.bf16.bf16.f32 "
        "{%0,%1,%2,%3}, {%4,%5,%6,%7}, {%8,%9}, {%0,%1,%2,%3};"
        : "+f"(d[0]), "+f"(d[1]), "+f"(d[2]), "+f"(d[3])
        : "r"(a[0]), "r"(a[1]), "r"(a[2]), "r"(a[3]), "r"(b0), "r"(b1));
}
__device__ __forceinline__ unsigned short bf_bits(__nv_bfloat16 b) {
    return *reinterpret_cast<unsigned short*>(&b);
}
__device__ __forceinline__ uint32_t cvt_bf2(float hi, float lo) {
    uint32_t r;
    asm("cvt.rn.bf16x2.f32 %0, %1, %2;" : "=r"(r) : "f"(hi), "f"(lo));
    return r;
}
__device__ __forceinline__ unsigned long long pack64(uint32_t lo, uint32_t hi) {
    unsigned long long v;
    asm("mov.b64 %0, {%1, %2};" : "=l"(v) : "r"(lo), "r"(hi));
    return v;
}
__device__ __forceinline__ void cpasync16(uint32_t dst, const void* src) {
    asm volatile("cp.async.ca.shared.global [%0], [%1], 16;"
        :: "r"(dst), "l"(src) : "memory");
}
__device__ __forceinline__ void cpasync_commit() {
    asm volatile("cp.async.commit_group;" ::: "memory");
}
__device__ __forceinline__ void cpasync_wait0() {
    asm volatile("cp.async.wait_group 0;" ::: "memory");
}

// ---------------------------------------------------------------------------
// Edge kernel. h = radial @ w1 on HMMA, 3-term bf16 hi/lo split, fp32 acc.
// B_hi fragments live in REGISTERS (loaded once); B_lo via paired x4.trans.
// Raw fp32 tiles double-buffered via cp.async.
// ---------------------------------------------------------------------------
__global__ __launch_bounds__(256, 2) void edge_kernel(
    const float* __restrict__ nbr_fea,
    const int*   __restrict__ nbr_idx,
    const float* __restrict__ w1,
    const float* __restrict__ b1,
    const float* __restrict__ w2,
    const float* __restrict__ b2)
{
    extern __shared__ char dyn[];
    const uint32_t raw_a = smem_u32(dyn);
    const uint32_t base  = (raw_a + 1023u) & ~1023u;
    char* bp = dyn + (base - raw_a);

    const int tid  = threadIdx.x;
    const int wid  = tid >> 5;
    const int lane = tid & 31;
    const int gid  = lane >> 2;     // row group 0-7
    const int tid4 = lane & 3;      // col group 0-3

    const int tile0   = blockIdx.x * TILES_PER_CTA;
    const int n_tiles = (tile0 + TILES_PER_CTA <= N_TILES_TOTAL)
                        ? TILES_PER_CTA : (N_TILES_TOTAL - tile0);
    if (n_tiles <= 0) return;

    // ---- stage B = w1 row-major [k][j], bf16 hi/lo, swizzled (once/CTA) ----
    #pragma unroll
    for (int it = 0; it < 16; it++) {
        int idx = it * 256 + tid;          // [0, 4096)
        int k = idx >> 6, j = idx & 63;
        float v = w1[idx];
        __nv_bfloat16 bh = __float2bfloat16(v);
        __nv_bfloat16 bl = __float2bfloat16(v - __bfloat162float(bh));
        uint32_t off = SMEM_SWZ((uint32_t)(k * 128 + j * 2));
        sts16(base + OFF_B_HI + off, bf_bits(bh));
        sts16(base + OFF_B_LO + off, bf_bits(bl));
    }
    if (tid < 32) {   // interleaved {b1[2t],b1[2t+1],w2[2t],w2[2t+1]}
        float4 bw;
        bw.x = b1[2 * tid];
        bw.y = b1[2 * tid + 1];
        bw.z = w2[(2 * tid) * SH_DIM];
        bw.w = w2[(2 * tid + 1) * SH_DIM];
        *(float4*)(bp + OFF_BW + tid * 16) = bw;
    }
    const float b2v = b2[0];

    // ---- async-prefetch tile 0 raw fp32 ----
    {
        const float* src = nbr_fea + (size_t)tile0 * TILE_E * NBR_F;
        #pragma unroll
        for (int it = 0; it < 8; it++) {
            int idx = it * 256 + tid;
            cpasync16(base + OFF_RAW + idx * 16, src + idx * 4);
        }
        cpasync_commit();
    }

    __syncthreads();   // B planes visible to all warps

    // ---- preload ALL B_hi fragments into registers (persist across tiles) ----
    // bhf[ks][ntp][0..3] = fragments for n-tiles 2*ntp, 2*ntp+1 at k-step ks
    uint32_t bhf[4][4][4];
    #pragma unroll
    for (int ks = 0; ks < 4; ks++)
        #pragma unroll
        for (int ntp = 0; ntp < 4; ntp++) {
            uint32_t boff = (uint32_t)((ks * 16 + (lane & 15)) * 128
                                       + (ntp * 2 + (lane >> 4)) * 16);
            ldsm_x4t(base + OFF_B_HI + SMEM_SWZ(boff), bhf[ks][ntp]);
        }

    for (int t = 0; t < n_tiles; t++) {
        const int tb = (tile0 + t) * TILE_E;

        // hoist idx loads for this tile (consumed at epilogue end)
        int ia0 = 0, ia1 = 0;
        if (tid4 == 0) {
            int r0 = wid * 16 + gid;
            ia0 = nbr_idx[tb + r0];
            ia1 = nbr_idx[tb + r0 + 8];
        }

        cpasync_wait0();
        __syncthreads();   // raw tile ready; prev tile's ldsm reads done

        // ---- convert raw (smem) -> A bf16 hi/lo planes ----
        #pragma unroll
        for (int it = 0; it < 8; it++) {
            int idx = it * 256 + tid;      // [0, 2048) float4 quads
            int row = idx >> 4, q = idx & 15;
            float4 v = *(const float4*)(bp + OFF_RAW + idx * 16);
            uint32_t h01 = cvt_bf2(v.y, v.x);
            uint32_t h23 = cvt_bf2(v.w, v.z);
            float f0 = __uint_as_float(h01 << 16);
            float f1 = __uint_as_float(h01 & 0xffff0000u);
            float f2 = __uint_as_float(h23 << 16);
            float f3 = __uint_as_float(h23 & 0xffff0000u);
            uint32_t l01 = cvt_bf2(v.y - f1, v.x - f0);
            uint32_t l23 = cvt_bf2(v.w - f3, v.z - f2);
            uint32_t off = SMEM_SWZ((uint32_t)(row * 128 + q * 8));
            sts64(base + OFF_A_HI + off, pack64(h01, h23));
            sts64(base + OFF_A_LO + off, pack64(l01, l23));
        }
        __syncthreads();   // A ready; raw buffer free for refill

        // ---- kick off next tile's raw prefetch (overlaps mainloop) ----
        if (t + 1 < n_tiles) {
            const float* src = nbr_fea + (size_t)(tb + TILE_E) * NBR_F;
            #pragma unroll
            for (int it = 0; it < 8; it++) {
                int idx = it * 256 + tid;
                cpasync16(base + OFF_RAW + idx * 16, src + idx * 4);
            }
            cpasync_commit();
        }

        // ---- mainloop: single fused pass over ks ----
        float acc[8][4];
        #pragma unroll
        for (int nt = 0; nt < 8; nt++)
            #pragma unroll
            for (int c = 0; c < 4; c++) acc[nt][c] = 0.0f;

        #pragma unroll
        for (int ks = 0; ks < 4; ks++) {
            uint32_t ah[4], al[4];
            uint32_t aoff = (uint32_t)((wid * 16 + (lane & 15)) * 128
                                       + ks * 32 + (lane >> 4) * 16);
            ldsm_x4(base + OFF_A_HI + SMEM_SWZ(aoff), ah);
            ldsm_x4(base + OFF_A_LO + SMEM_SWZ(aoff), al);
            #pragma unroll
            for (int ntp = 0; ntp < 4; ntp++) {
                uint32_t bl[4];
                uint32_t boff = (uint32_t)((ks * 16 + (lane & 15)) * 128
                                           + (ntp * 2 + (lane >> 4)) * 16);
                ldsm_x4t(base + OFF_B_LO + SMEM_SWZ(boff), bl);
                const uint32_t* bh = bhf[ks][ntp];
                mma_bf16(acc[2 * ntp],     ah, bh[0], bh[1]);
                mma_bf16(acc[2 * ntp],     al, bh[0], bh[1]);
                mma_bf16(acc[2 * ntp],     ah, bl[0], bl[1]);
                mma_bf16(acc[2 * ntp + 1], ah, bh[2], bh[3]);
                mma_bf16(acc[2 * ntp + 1], al, bh[2], bh[3]);
                mma_bf16(acc[2 * ntp + 1], ah, bl[2], bl[3]);
            }
        }

        // ---- epilogue: softplus . w2, quad-reduce, atomics ----
        float s0 = 0.0f, s1 = 0.0f;
        #pragma unroll
        for (int nt = 0; nt < 8; nt++) {
            int colp = nt * 4 + tid4;     // float4 index = col/2
            float4 bw = *(const float4*)(bp + OFF_BW + colp * 16);
            float h0 = acc[nt][0] + bw.x;   // row gid
            float h1 = acc[nt][1] + bw.y;
            float h2 = acc[nt][2] + bw.x;   // row gid+8
            float h3 = acc[nt][3] + bw.y;
            float p0 = fmaxf(h0, 0.0f) + __logf(1.0f + __expf(-fabsf(h0)));
            float p1 = fmaxf(h1, 0.0f) + __logf(1.0f + __expf(-fabsf(h1)));
            float p2 = fmaxf(h2, 0.0f) + __logf(1.0f + __expf(-fabsf(h2)));
            float p3 = fmaxf(h3, 0.0f) + __logf(1.0f + __expf(-fabsf(h3)));
            s0 = fmaf(p0, bw.z, s0); s0 = fmaf(p1, bw.w, s0);
            s1 = fmaf(p2, bw.z, s1); s1 = fmaf(p3, bw.w, s1);
        }
        s0 += __shfl_xor_sync(0xffffffffu, s0, 1);
        s0 += __shfl_xor_sync(0xffffffffu, s0, 2);
        s1 += __shfl_xor_sync(0xffffffffu, s1, 1);
        s1 += __shfl_xor_sync(0xffffffffu, s1, 2);
        if (tid4 == 0) {
            int a0 = ia0;
            a0 = (a0 < 0) ? 0 : (a0 >= N_ATOMS ? N_ATOMS - 1 : a0);
            atomicAdd(&g_S[a0], s0 + b2v);
            atomicAdd(&g_C[a0], 1.0f);
            int a1 = ia1;
            a1 = (a1 < 0) ? 0 : (a1 >= N_ATOMS ? N_ATOMS - 1 : a1);
            atomicAdd(&g_S[a1], s1 + b2v);
            atomicAdd(&g_C[a1], 1.0f);
        }
    }
}

// ---------------------------------------------------------------------------
// Output GEMM on HMMA. 4 atom-tiles (64 atoms each) per CTA: tp_w staged once.
// B loads via paired x4.trans (half the ldmatrix count).
// ---------------------------------------------------------------------------
#define OT_M 64
#define OT_TILES 4
#define N_OUT_CTAS ((N_ATOMS + OT_M * OT_TILES - 1) / (OT_M * OT_TILES))   // 196

#define O_A_HI 0        // 2 kc-planes x 8192 (64 rows x 128B)
#define O_A_LO 16384
#define O_B_HI 32768    // 4 planes [kc][ch] x 8192
#define O_B_LO 65536
#define OUT_SMEM_USED 98304
#define OUT_SMEM_BYTES (OUT_SMEM_USED + 1024)

__global__ __launch_bounds__(256, 2) void out_kernel(
    const float* __restrict__ atom_fea,
    const float* __restrict__ tp_w,
    float* __restrict__ out)
{
    extern __shared__ char dyn[];
    const uint32_t raw_a = smem_u32(dyn);
    const uint32_t base  = (raw_a + 1023u) & ~1023u;

    const int tid  = threadIdx.x;
    const int wid  = tid >> 5;
    const int lane = tid & 31;
    const int gid  = lane >> 2;
    const int tid4 = lane & 3;
    const int mt   = wid & 3;       // m-tile (16 atoms)
    const int ch   = wid >> 2;      // col half (64 cols)

    // ---- stage B = tp_w [k][j] bf16 hi/lo into 4 planes [kc][jh] (once) ----
    #pragma unroll
    for (int it = 0; it < 64; it++) {
        int idx = it * 256 + tid;          // [0, 16384)
        int k = idx >> 7, j = idx & 127;
        float v = tp_w[idx];
        __nv_bfloat16 bh = __float2bfloat16(v);
        __nv_bfloat16 bl = __float2bfloat16(v - __bfloat162float(bh));
        uint32_t plane = (uint32_t)(((k >> 6) * 2 + (j >> 6)) * 8192);
        uint32_t off = plane + SMEM_SWZ((uint32_t)((k & 63) * 128 + (j & 63) * 2));
        sts16(base + O_B_HI + off, bf_bits(bh));
        sts16(base + O_B_LO + off, bf_bits(bl));
    }

    for (int t = 0; t < OT_TILES; t++) {
        const int abase = (blockIdx.x * OT_TILES + t) * OT_M;
        if (abase >= N_ATOMS) break;

        __syncthreads();   // B ready (t==0) / prev tile's A reads done

        // ---- stage A tile (64 atoms x 128 k) bf16 hi/lo, 2 kc planes ----
        #pragma unroll
        for (int it = 0; it < 8; it++) {
            int idx = it * 256 + tid;          // [0, 2048) float4 quads
            int row = idx >> 5, q = idx & 31;
            int kc = q >> 4, qq = q & 15;
            int atom = abase + row;
            float4 v = make_float4(0.f, 0.f, 0.f, 0.f);
            if (atom < N_ATOMS)
                v = *(const float4*)(atom_fea + (size_t)atom * ATOM_F + q * 4);
            uint32_t h01 = cvt_bf2(v.y, v.x);
            uint32_t h23 = cvt_bf2(v.w, v.z);
            float f0 = __uint_as_float(h01 << 16);
            float f1 = __uint_as_float(h01 & 0xffff0000u);
            float f2 = __uint_as_float(h23 << 16);
            float f3 = __uint_as_float(h23 & 0xffff0000u);
            uint32_t l01 = cvt_bf2(v.y - f1, v.x - f0);
            uint32_t l23 = cvt_bf2(v.w - f3, v.z - f2);
            uint32_t off = (uint32_t)(kc * 8192)
                         + SMEM_SWZ((uint32_t)(row * 128 + qq * 8));
            sts64(base + O_A_HI + off, pack64(h01, h23));
            sts64(base + O_A_LO + off, pack64(l01, l23));
        }
        __syncthreads();

        // ---- mainloop: 2 k-chunks x 4 ks, paired-nt B loads ----
        float acc[8][4];
        #pragma unroll
        for (int nt = 0; nt < 8; nt++)
            #pragma unroll
            for (int c = 0; c < 4; c++) acc[nt][c] = 0.0f;

        #pragma unroll
        for (int kc = 0; kc < 2; kc++) {
            const uint32_t apl = (uint32_t)(kc * 8192);
            const uint32_t bpl = (uint32_t)((kc * 2 + ch) * 8192);
            #pragma unroll
            for (int ks = 0; ks < 4; ks++) {
                uint32_t ah[4], al[4];
                uint32_t aoff = apl + SMEM_SWZ((uint32_t)((mt * 16 + (lane & 15)) * 128
                                               + ks * 32 + (lane >> 4) * 16));
                ldsm_x4(base + O_A_HI + aoff, ah);
                ldsm_x4(base + O_A_LO + aoff, al);
                #pragma unroll
                for (int ntp = 0; ntp < 4; ntp++) {
                    uint32_t boff = bpl + SMEM_SWZ((uint32_t)((ks * 16 + (lane & 15)) * 128
                                                   + (ntp * 2 + (lane >> 4)) * 16));
                    uint32_t bh4[4], bl4[4];
                    ldsm_x4t(base + O_B_HI + boff, bh4);
                    ldsm_x4t(base + O_B_LO + boff, bl4);
                    mma_bf16(acc[2 * ntp],     ah, bh4[0], bh4[1]);
                    mma_bf16(acc[2 * ntp],     al, bh4[0], bh4[1]);
                    mma_bf16(acc[2 * ntp],     ah, bl4[0], bl4[1]);
                    mma_bf16(acc[2 * ntp + 1], ah, bh4[2], bh4[3]);
                    mma_bf16(acc[2 * ntp + 1], al, bh4[2], bh4[3]);
                    mma_bf16(acc[2 * ntp + 1], ah, bl4[2], bl4[3]);
                }
            }
        }

        // ---- epilogue: per-atom scale, write float2 pairs ----
        int atomA = abase + mt * 16 + gid;
        int atomB = atomA + 8;
        float scA = 0.0f, scB = 0.0f;
        if (atomA < N_ATOMS)
            scA = g_S[atomA] * INV_SQRT_F / fmaxf(g_C[atomA], 1.0f);
        if (atomB < N_ATOMS)
            scB = g_S[atomB] * INV_SQRT_F / fmaxf(g_C[atomB], 1.0f);

        #pragma unroll
        for (int nt = 0; nt < 8; nt++) {
            int col = ch * 64 + nt * 8 + tid4 * 2;
            if (atomA < N_ATOMS)
                *(float2*)(out + (size_t)atomA * ATOM_F + col) =
                    make_float2(acc[nt][0] * scA, acc[nt][1] * scA);
            if (atomB < N_ATOMS)
                *(float2*)(out + (size_t)atomB * ATOM_F + col) =
                    make_float2(acc[nt][2] * scB, acc[nt][3] * scB);
        }
    }
}

// ---------------------------------------------------------------------------
// Launch
// ---------------------------------------------------------------------------
extern "C" void kernel_launch(void* const* d_in, const int* in_sizes, int n_in,
                              void* d_out, int out_size)
{
    const float* atom_fea = (const float*)d_in[0];
    const float* nbr_fea  = (const float*)d_in[1];
    const int*   nbr_idx  = (const int*)d_in[2];
    const float* w1       = (const float*)d_in[3];
    const float* b1       = (const float*)d_in[4];
    const float* w2       = (const float*)d_in[5];
    const float* b2       = (const float*)d_in[6];
    const float* tp_w     = (const float*)d_in[7];
    float*       out      = (float*)d_out;

    cudaFuncSetAttribute(edge_kernel,
                         cudaFuncAttributeMaxDynamicSharedMemorySize,
                         EDGE_SMEM_BYTES);
    cudaFuncSetAttribute(out_kernel,
                         cudaFuncAttributeMaxDynamicSharedMemorySize,
                         OUT_SMEM_BYTES);

    zero_kernel<<<(N_ATOMS + 255) / 256, 256>>>();
    edge_kernel<<<N_EDGE_CTAS, 256, EDGE_SMEM_BYTES>>>(nbr_fea, nbr_idx,
                                                       w1, b1, w2, b2);
    out_kernel<<<N_OUT_CTAS, 256, OUT_SMEM_BYTES>>>(atom_fea, tp_w, out);
}

// round 13
// speedup vs baseline: 1.2667x; 1.2667x over previous
#include <cuda_runtime.h>
#include <cuda_bf16.h>
#include <cstdint>

#define N_ATOMS 50000
#define M_NBR   32
#define NE      (N_ATOMS * M_NBR)   // 1,600,000 edges
#define NBR_F   64
#define ATOM_F  128
#define SH_DIM  9
#define INV_SQRT_F 0.08838834764831845f

#define TILE_E        128            // edges per tile (8 warps x 16 edges)
#define TILES_PER_CTA 8
#define N_TILES_TOTAL (NE / TILE_E)              // 12500
#define N_EDGE_CTAS   ((N_TILES_TOTAL + TILES_PER_CTA - 1) / TILES_PER_CTA)  // 1563

// ---- edge-kernel smem layout (byte offsets from 1024-aligned base) ----
#define OFF_A_HI   0                 // 128 x 64 bf16, swizzled 128B rows (16384)
#define OFF_A_LO   16384             // 16384
#define OFF_B_HI   32768             // 64 x 64 bf16 row-major [k][j], swz (8192)
#define OFF_B_LO   40960             // 8192
#define OFF_BW     49152             // 32 x float4 {b1[2j],b1[2j+1],w2[2j],w2[2j+1]}
#define OFF_RAW    49664             // 128 x 64 f32 raw tile (32768)
#define EDGE_SMEM_USED 82432
#define EDGE_SMEM_BYTES (EDGE_SMEM_USED + 1024)

__device__ float g_S[N_ATOMS];
__device__ float g_C[N_ATOMS];

__global__ void zero_kernel() {
    int i = blockIdx.x * blockDim.x + threadIdx.x;
    if (i < N_ATOMS) { g_S[i] = 0.0f; g_C[i] = 0.0f; }
}

// ======================= helpers =======================
__device__ __forceinline__ uint32_t smem_u32(const void* p) {
    uint32_t a;
    asm("{ .reg .u64 t; cvta.to.shared.u64 t, %1; cvt.u32.u64 %0, t; }"
        : "=r"(a) : "l"(p));
    return a;
}
__device__ __forceinline__ void sts64(uint32_t addr, unsigned long long v) {
    asm volatile("st.shared.b64 [%0], %1;" :: "r"(addr), "l"(v) : "memory");
}
__device__ __forceinline__ void sts16(uint32_t addr, unsigned short v) {
    asm volatile("st.shared.b16 [%0], %1;" :: "r"(addr), "h"(v) : "memory");
}
#define SMEM_SWZ(off) ((off) ^ (((off) >> 3) & 0x70))

__device__ __forceinline__ void ldsm_x4(uint32_t addr, uint32_t* r) {
    asm volatile("ldmatrix.sync.aligned.m8n8.x4.shared.b16 {%0,%1,%2,%3}, [%4];"
        : "=r"(r[0]), "=r"(r[1]), "=r"(r[2]), "=r"(r[3]) : "r"(addr));
}
// x4 trans: loads TWO n-tiles' B fragments (lanes 0-15 -> nt, 16-31 -> nt+1)
__device__ __forceinline__ void ldsm_x4t(uint32_t addr, uint32_t* r) {
    asm volatile("ldmatrix.sync.aligned.m8n8.x4.trans.shared.b16 {%0,%1,%2,%3}, [%4];"
        : "=r"(r[0]), "=r"(r[1]), "=r"(r[2]), "=r"(r[3]) : "r"(addr));
}
__device__ __forceinline__ void mma_bf16(float* d, const uint32_t* a,
                                         uint32_t b0, uint32_t b1) {
    asm volatile("mma.sync.aligned.m16n8k16.row.col.f32.bf16.bf16.f32 "
        "{%0,%1,%2,%3}, {%4,%5,%6,%7}, {%8,%9}, {%0,%1,%2,%3};"
        : "+f"(d[0]), "+f"(d[1]), "+f"(d[2]), "+f"(d[3])
        : "r"(a[0]), "r"(a[1]), "r"(a[2]), "r"(a[3]), "r"(b0), "r"(b1));
}
__device__ __forceinline__ unsigned short bf_bits(__nv_bfloat16 b) {
    return *reinterpret_cast<unsigned short*>(&b);
}
__device__ __forceinline__ uint32_t cvt_bf2(float hi, float lo) {
    uint32_t r;
    asm("cvt.rn.bf16x2.f32 %0, %1, %2;" : "=r"(r) : "f"(hi), "f"(lo));
    return r;
}
__device__ __forceinline__ unsigned long long pack64(uint32_t lo, uint32_t hi) {
    unsigned long long v;
    asm("mov.b64 %0, {%1, %2};" : "=l"(v) : "r"(lo), "r"(hi));
    return v;
}
__device__ __forceinline__ void cpasync16(uint32_t dst, const void* src) {
    asm volatile("cp.async.ca.shared.global [%0], [%1], 16;"
        :: "r"(dst), "l"(src) : "memory");
}
__device__ __forceinline__ void cpasync_commit() {
    asm volatile("cp.async.commit_group;" ::: "memory");
}
__device__ __forceinline__ void cpasync_wait0() {
    asm volatile("cp.async.wait_group 0;" ::: "memory");
}

// ---------------------------------------------------------------------------
// Edge kernel (R10 structure): h = radial @ w1 on HMMA, 3-term bf16 hi/lo,
// fp32 acc. cp.async double-buffered raw tiles. B loads use paired x4.trans
// (two n-tiles per ldmatrix; fragments consumed immediately — no reg cost).
// ---------------------------------------------------------------------------
__global__ __launch_bounds__(256, 2) void edge_kernel(
    const float* __restrict__ nbr_fea,
    const int*   __restrict__ nbr_idx,
    const float* __restrict__ w1,
    const float* __restrict__ b1,
    const float* __restrict__ w2,
    const float* __restrict__ b2)
{
    extern __shared__ char dyn[];
    const uint32_t raw_a = smem_u32(dyn);
    const uint32_t base  = (raw_a + 1023u) & ~1023u;
    char* bp = dyn + (base - raw_a);

    const int tid  = threadIdx.x;
    const int wid  = tid >> 5;
    const int lane = tid & 31;
    const int gid  = lane >> 2;     // row group 0-7
    const int tid4 = lane & 3;      // col group 0-3

    const int tile0   = blockIdx.x * TILES_PER_CTA;
    const int n_tiles = (tile0 + TILES_PER_CTA <= N_TILES_TOTAL)
                        ? TILES_PER_CTA : (N_TILES_TOTAL - tile0);
    if (n_tiles <= 0) return;

    // ---- stage B = w1 row-major [k][j], bf16 hi/lo, swizzled (once/CTA) ----
    #pragma unroll
    for (int it = 0; it < 16; it++) {
        int idx = it * 256 + tid;          // [0, 4096)
        int k = idx >> 6, j = idx & 63;
        float v = w1[idx];
        __nv_bfloat16 bh = __float2bfloat16(v);
        __nv_bfloat16 bl = __float2bfloat16(v - __bfloat162float(bh));
        uint32_t off = SMEM_SWZ((uint32_t)(k * 128 + j * 2));
        sts16(base + OFF_B_HI + off, bf_bits(bh));
        sts16(base + OFF_B_LO + off, bf_bits(bl));
    }
    if (tid < 32) {   // interleaved {b1[2t],b1[2t+1],w2[2t],w2[2t+1]}
        float4 bw;
        bw.x = b1[2 * tid];
        bw.y = b1[2 * tid + 1];
        bw.z = w2[(2 * tid) * SH_DIM];
        bw.w = w2[(2 * tid + 1) * SH_DIM];
        *(float4*)(bp + OFF_BW + tid * 16) = bw;
    }
    const float b2v = b2[0];

    // ---- async-prefetch tile 0 raw fp32 ----
    {
        const float* src = nbr_fea + (size_t)tile0 * TILE_E * NBR_F;
        #pragma unroll
        for (int it = 0; it < 8; it++) {
            int idx = it * 256 + tid;
            cpasync16(base + OFF_RAW + idx * 16, src + idx * 4);
        }
        cpasync_commit();
    }

    for (int t = 0; t < n_tiles; t++) {
        const int tb = (tile0 + t) * TILE_E;

        // hoist idx loads for this tile (consumed at epilogue end)
        int ia0 = 0, ia1 = 0;
        if (tid4 == 0) {
            int r0 = wid * 16 + gid;
            ia0 = nbr_idx[tb + r0];
            ia1 = nbr_idx[tb + r0 + 8];
        }

        cpasync_wait0();
        __syncthreads();   // raw tile ready; prev tile's ldsm reads done

        // ---- convert raw (smem) -> A bf16 hi/lo planes ----
        #pragma unroll
        for (int it = 0; it < 8; it++) {
            int idx = it * 256 + tid;      // [0, 2048) float4 quads
            int row = idx >> 4, q = idx & 15;
            float4 v = *(const float4*)(bp + OFF_RAW + idx * 16);
            uint32_t h01 = cvt_bf2(v.y, v.x);
            uint32_t h23 = cvt_bf2(v.w, v.z);
            float f0 = __uint_as_float(h01 << 16);
            float f1 = __uint_as_float(h01 & 0xffff0000u);
            float f2 = __uint_as_float(h23 << 16);
            float f3 = __uint_as_float(h23 & 0xffff0000u);
            uint32_t l01 = cvt_bf2(v.y - f1, v.x - f0);
            uint32_t l23 = cvt_bf2(v.w - f3, v.z - f2);
            uint32_t off = SMEM_SWZ((uint32_t)(row * 128 + q * 8));
            sts64(base + OFF_A_HI + off, pack64(h01, h23));
            sts64(base + OFF_A_LO + off, pack64(l01, l23));
        }
        __syncthreads();   // A ready; raw buffer free for refill

        // ---- kick off next tile's raw prefetch (overlaps mainloop) ----
        if (t + 1 < n_tiles) {
            const float* src = nbr_fea + (size_t)(tb + TILE_E) * NBR_F;
            #pragma unroll
            for (int it = 0; it < 8; it++) {
                int idx = it * 256 + tid;
                cpasync16(base + OFF_RAW + idx * 16, src + idx * 4);
            }
            cpasync_commit();
        }

        // ---- mainloop ----
        float acc[8][4];
        #pragma unroll
        for (int nt = 0; nt < 8; nt++)
            #pragma unroll
            for (int c = 0; c < 4; c++) acc[nt][c] = 0.0f;

        // Pass 1: (A_hi + A_lo) . B_hi — paired-nt x4.trans B loads
        #pragma unroll
        for (int ks = 0; ks < 4; ks++) {
            uint32_t ah[4], al[4];
            uint32_t aoff = (uint32_t)((wid * 16 + (lane & 15)) * 128
                                       + ks * 32 + (lane >> 4) * 16);
            ldsm_x4(base + OFF_A_HI + SMEM_SWZ(aoff), ah);
            ldsm_x4(base + OFF_A_LO + SMEM_SWZ(aoff), al);
            #pragma unroll
            for (int ntp = 0; ntp < 4; ntp++) {
                uint32_t bh4[4];
                uint32_t boff = (uint32_t)((ks * 16 + (lane & 15)) * 128
                                           + (ntp * 2 + (lane >> 4)) * 16);
                ldsm_x4t(base + OFF_B_HI + SMEM_SWZ(boff), bh4);
                mma_bf16(acc[2 * ntp],     ah, bh4[0], bh4[1]);
                mma_bf16(acc[2 * ntp],     al, bh4[0], bh4[1]);
                mma_bf16(acc[2 * ntp + 1], ah, bh4[2], bh4[3]);
                mma_bf16(acc[2 * ntp + 1], al, bh4[2], bh4[3]);
            }
        }
        // Pass 2: A_hi . B_lo — paired-nt x4.trans B loads
        #pragma unroll
        for (int ks = 0; ks < 4; ks++) {
            uint32_t ah[4];
            uint32_t aoff = (uint32_t)((wid * 16 + (lane & 15)) * 128
                                       + ks * 32 + (lane >> 4) * 16);
            ldsm_x4(base + OFF_A_HI + SMEM_SWZ(aoff), ah);
            #pragma unroll
            for (int ntp = 0; ntp < 4; ntp++) {
                uint32_t bl4[4];
                uint32_t boff = (uint32_t)((ks * 16 + (lane & 15)) * 128
                                           + (ntp * 2 + (lane >> 4)) * 16);
                ldsm_x4t(base + OFF_B_LO + SMEM_SWZ(boff), bl4);
                mma_bf16(acc[2 * ntp],     ah, bl4[0], bl4[1]);
                mma_bf16(acc[2 * ntp + 1], ah, bl4[2], bl4[3]);
            }
        }

        // ---- epilogue: softplus . w2, quad-reduce, atomics ----
        float s0 = 0.0f, s1 = 0.0f;
        #pragma unroll
        for (int nt = 0; nt < 8; nt++) {
            int colp = nt * 4 + tid4;     // float4 index = col/2
            float4 bw = *(const float4*)(bp + OFF_BW + colp * 16);
            float h0 = acc[nt][0] + bw.x;   // row gid
            float h1 = acc[nt][1] + bw.y;
            float h2 = acc[nt][2] + bw.x;   // row gid+8
            float h3 = acc[nt][3] + bw.y;
            float p0 = fmaxf(h0, 0.0f) + __logf(1.0f + __expf(-fabsf(h0)));
            float p1 = fmaxf(h1, 0.0f) + __logf(1.0f + __expf(-fabsf(h1)));
            float p2 = fmaxf(h2, 0.0f) + __logf(1.0f + __expf(-fabsf(h2)));
            float p3 = fmaxf(h3, 0.0f) + __logf(1.0f + __expf(-fabsf(h3)));
            s0 = fmaf(p0, bw.z, s0); s0 = fmaf(p1, bw.w, s0);
            s1 = fmaf(p2, bw.z, s1); s1 = fmaf(p3, bw.w, s1);
        }
        s0 += __shfl_xor_sync(0xffffffffu, s0, 1);
        s0 += __shfl_xor_sync(0xffffffffu, s0, 2);
        s1 += __shfl_xor_sync(0xffffffffu, s1, 1);
        s1 += __shfl_xor_sync(0xffffffffu, s1, 2);
        if (tid4 == 0) {
            int a0 = ia0;
            a0 = (a0 < 0) ? 0 : (a0 >= N_ATOMS ? N_ATOMS - 1 : a0);
            atomicAdd(&g_S[a0], s0 + b2v);
            atomicAdd(&g_C[a0], 1.0f);
            int a1 = ia1;
            a1 = (a1 < 0) ? 0 : (a1 >= N_ATOMS ? N_ATOMS - 1 : a1);
            atomicAdd(&g_S[a1], s1 + b2v);
            atomicAdd(&g_C[a1], 1.0f);
        }
    }
}

// ---------------------------------------------------------------------------
// Output GEMM on HMMA (R10 structure: 1 tile of 64 atoms per CTA, 782 CTAs).
// B loads use paired x4.trans.
// ---------------------------------------------------------------------------
#define OT_M 64
#define N_OUT_CTAS ((N_ATOMS + OT_M - 1) / OT_M)   // 782

#define O_A_HI 0        // 2 kc-planes x 8192 (64 rows x 128B)
#define O_A_LO 16384
#define O_B_HI 32768    // 4 planes [kc][ch] x 8192
#define O_B_LO 65536
#define OUT_SMEM_USED 98304
#define OUT_SMEM_BYTES (OUT_SMEM_USED + 1024)

__global__ __launch_bounds__(256, 2) void out_kernel(
    const float* __restrict__ atom_fea,
    const float* __restrict__ tp_w,
    float* __restrict__ out)
{
    extern __shared__ char dyn[];
    const uint32_t raw_a = smem_u32(dyn);
    const uint32_t base  = (raw_a + 1023u) & ~1023u;

    const int tid  = threadIdx.x;
    const int wid  = tid >> 5;
    const int lane = tid & 31;
    const int gid  = lane >> 2;
    const int tid4 = lane & 3;
    const int mt   = wid & 3;       // m-tile (16 atoms)
    const int ch   = wid >> 2;      // col half (64 cols)
    const int abase = blockIdx.x * OT_M;

    // ---- stage B = tp_w [k][j] bf16 hi/lo into 4 planes [kc][jh] ----
    #pragma unroll
    for (int it = 0; it < 64; it++) {
        int idx = it * 256 + tid;          // [0, 16384)
        int k = idx >> 7, j = idx & 127;
        float v = tp_w[idx];
        __nv_bfloat16 bh = __float2bfloat16(v);
        __nv_bfloat16 bl = __float2bfloat16(v - __bfloat162float(bh));
        uint32_t plane = (uint32_t)(((k >> 6) * 2 + (j >> 6)) * 8192);
        uint32_t off = plane + SMEM_SWZ((uint32_t)((k & 63) * 128 + (j & 63) * 2));
        sts16(base + O_B_HI + off, bf_bits(bh));
        sts16(base + O_B_LO + off, bf_bits(bl));
    }

    // ---- stage A = atom_fea tile (64 atoms x 128 k) bf16 hi/lo, 2 kc planes ----
    #pragma unroll
    for (int it = 0; it < 8; it++) {
        int idx = it * 256 + tid;          // [0, 2048) float4 quads
        int row = idx >> 5, q = idx & 31;
        int kc = q >> 4, qq = q & 15;
        int atom = abase + row;
        float4 v = make_float4(0.f, 0.f, 0.f, 0.f);
        if (atom < N_ATOMS)
            v = *(const float4*)(atom_fea + (size_t)atom * ATOM_F + q * 4);
        uint32_t h01 = cvt_bf2(v.y, v.x);
        uint32_t h23 = cvt_bf2(v.w, v.z);
        float f0 = __uint_as_float(h01 << 16);
        float f1 = __uint_as_float(h01 & 0xffff0000u);
        float f2 = __uint_as_float(h23 << 16);
        float f3 = __uint_as_float(h23 & 0xffff0000u);
        uint32_t l01 = cvt_bf2(v.y - f1, v.x - f0);
        uint32_t l23 = cvt_bf2(v.w - f3, v.z - f2);
        uint32_t off = (uint32_t)(kc * 8192)
                     + SMEM_SWZ((uint32_t)(row * 128 + qq * 8));
        sts64(base + O_A_HI + off, pack64(h01, h23));
        sts64(base + O_A_LO + off, pack64(l01, l23));
    }
    __syncthreads();

    // ---- mainloop: 2 k-chunks x 4 ks, paired-nt B loads ----
    float acc[8][4];
    #pragma unroll
    for (int nt = 0; nt < 8; nt++)
        #pragma unroll
        for (int c = 0; c < 4; c++) acc[nt][c] = 0.0f;

    #pragma unroll
    for (int kc = 0; kc < 2; kc++) {
        const uint32_t apl = (uint32_t)(kc * 8192);
        const uint32_t bpl = (uint32_t)((kc * 2 + ch) * 8192);
        #pragma unroll
        for (int ks = 0; ks < 4; ks++) {
            uint32_t ah[4], al[4];
            uint32_t aoff = apl + SMEM_SWZ((uint32_t)((mt * 16 + (lane & 15)) * 128
                                           + ks * 32 + (lane >> 4) * 16));
            ldsm_x4(base + O_A_HI + aoff, ah);
            ldsm_x4(base + O_A_LO + aoff, al);
            #pragma unroll
            for (int ntp = 0; ntp < 4; ntp++) {
                uint32_t boff = bpl + SMEM_SWZ((uint32_t)((ks * 16 + (lane & 15)) * 128
                                               + (ntp * 2 + (lane >> 4)) * 16));
                uint32_t bh4[4], bl4[4];
                ldsm_x4t(base + O_B_HI + boff, bh4);
                ldsm_x4t(base + O_B_LO + boff, bl4);
                mma_bf16(acc[2 * ntp],     ah, bh4[0], bh4[1]);
                mma_bf16(acc[2 * ntp],     al, bh4[0], bh4[1]);
                mma_bf16(acc[2 * ntp],     ah, bl4[0], bl4[1]);
                mma_bf16(acc[2 * ntp + 1], ah, bh4[2], bh4[3]);
                mma_bf16(acc[2 * ntp + 1], al, bh4[2], bh4[3]);
                mma_bf16(acc[2 * ntp + 1], ah, bl4[2], bl4[3]);
            }
        }
    }

    // ---- epilogue: per-atom scale, write float2 pairs ----
    int atomA = abase + mt * 16 + gid;
    int atomB = atomA + 8;
    float scA = 0.0f, scB = 0.0f;
    if (atomA < N_ATOMS)
        scA = g_S[atomA] * INV_SQRT_F / fmaxf(g_C[atomA], 1.0f);
    if (atomB < N_ATOMS)
        scB = g_S[atomB] * INV_SQRT_F / fmaxf(g_C[atomB], 1.0f);

    #pragma unroll
    for (int nt = 0; nt < 8; nt++) {
        int col = ch * 64 + nt * 8 + tid4 * 2;
        if (atomA < N_ATOMS)
            *(float2*)(out + (size_t)atomA * ATOM_F + col) =
                make_float2(acc[nt][0] * scA, acc[nt][1] * scA);
        if (atomB < N_ATOMS)
            *(float2*)(out + (size_t)atomB * ATOM_F + col) =
                make_float2(acc[nt][2] * scB, acc[nt][3] * scB);
    }
}

// ---------------------------------------------------------------------------
// Launch
// ---------------------------------------------------------------------------
extern "C" void kernel_launch(void* const* d_in, const int* in_sizes, int n_in,
                              void* d_out, int out_size)
{
    const float* atom_fea = (const float*)d_in[0];
    const float* nbr_fea  = (const float*)d_in[1];
    const int*   nbr_idx  = (const int*)d_in[2];
    const float* w1       = (const float*)d_in[3];
    const float* b1       = (const float*)d_in[4];
    const float* w2       = (const float*)d_in[5];
    const float* b2       = (const float*)d_in[6];
    const float* tp_w     = (const float*)d_in[7];
    float*       out      = (float*)d_out;

    cudaFuncSetAttribute(edge_kernel,
                         cudaFuncAttributeMaxDynamicSharedMemorySize,
                         EDGE_SMEM_BYTES);
    cudaFuncSetAttribute(out_kernel,
                         cudaFuncAttributeMaxDynamicSharedMemorySize,
                         OUT_SMEM_BYTES);

    zero_kernel<<<(N_ATOMS + 255) / 256, 256>>>();
    edge_kernel<<<N_EDGE_CTAS, 256, EDGE_SMEM_BYTES>>>(nbr_fea, nbr_idx,
                                                       w1, b1, w2, b2);
    out_kernel<<<N_OUT_CTAS, 256, OUT_SMEM_BYTES>>>(atom_fea, tp_w, out);
}

// round 14
// speedup vs baseline: 1.2909x; 1.0191x over previous
#include <cuda_runtime.h>
#include <cuda_bf16.h>
#include <cstdint>

#define N_ATOMS 50000
#define M_NBR   32
#define NE      (N_ATOMS * M_NBR)   // 1,600,000 edges
#define NBR_F   64
#define ATOM_F  128
#define SH_DIM  9
#define INV_SQRT_F 0.08838834764831845f

#define TILE_E        128            // edges per tile (8 warps x 16 edges)
#define TILES_PER_CTA 8
#define N_TILES_TOTAL (NE / TILE_E)              // 12500
#define N_EDGE_CTAS   ((N_TILES_TOTAL + TILES_PER_CTA - 1) / TILES_PER_CTA)  // 1563

// ---- edge-kernel smem layout (byte offsets from 1024-aligned base) ----
#define OFF_A_HI   0                 // 128 x 64 bf16, swizzled 128B rows (16384)
#define OFF_A_LO   16384             // 16384
#define OFF_B_HI   32768             // 64 x 64 bf16 row-major [k][j], swz (8192)
#define OFF_B_LO   40960             // 8192
#define OFF_BW     49152             // 32 x float4 {b1[2j],b1[2j+1],w2[2j],w2[2j+1]}
#define OFF_RAW    49664             // 128 x 64 f32 raw tile (32768)
#define EDGE_SMEM_USED 82432
#define EDGE_SMEM_BYTES (EDGE_SMEM_USED + 1024)

__device__ float g_S[N_ATOMS];
__device__ float g_C[N_ATOMS];

__global__ void zero_kernel() {
    int i = blockIdx.x * blockDim.x + threadIdx.x;
    if (i < N_ATOMS) { g_S[i] = 0.0f; g_C[i] = 0.0f; }
}

// ======================= helpers =======================
__device__ __forceinline__ uint32_t smem_u32(const void* p) {
    uint32_t a;
    asm("{ .reg .u64 t; cvta.to.shared.u64 t, %1; cvt.u32.u64 %0, t; }"
        : "=r"(a) : "l"(p));
    return a;
}
__device__ __forceinline__ void sts64(uint32_t addr, unsigned long long v) {
    asm volatile("st.shared.b64 [%0], %1;" :: "r"(addr), "l"(v) : "memory");
}
__device__ __forceinline__ void sts32(uint32_t addr, uint32_t v) {
    asm volatile("st.shared.b32 [%0], %1;" :: "r"(addr), "r"(v) : "memory");
}
__device__ __forceinline__ void sts16(uint32_t addr, unsigned short v) {
    asm volatile("st.shared.b16 [%0], %1;" :: "r"(addr), "h"(v) : "memory");
}
#define SMEM_SWZ(off) ((off) ^ (((off) >> 3) & 0x70))

__device__ __forceinline__ void ldsm_x4(uint32_t addr, uint32_t* r) {
    asm volatile("ldmatrix.sync.aligned.m8n8.x4.shared.b16 {%0,%1,%2,%3}, [%4];"
        : "=r"(r[0]), "=r"(r[1]), "=r"(r[2]), "=r"(r[3]) : "r"(addr));
}
__device__ __forceinline__ void ldsm_x2t(uint32_t addr, uint32_t& a, uint32_t& b) {
    asm volatile("ldmatrix.sync.aligned.m8n8.x2.trans.shared.b16 {%0,%1}, [%2];"
        : "=r"(a), "=r"(b) : "r"(addr));
}
// x4 trans: loads TWO n-tiles' B fragments (lanes 0-15 -> nt, 16-31 -> nt+1)
__device__ __forceinline__ void ldsm_x4t(uint32_t addr, uint32_t* r) {
    asm volatile("ldmatrix.sync.aligned.m8n8.x4.trans.shared.b16 {%0,%1,%2,%3}, [%4];"
        : "=r"(r[0]), "=r"(r[1]), "=r"(r[2]), "=r"(r[3]) : "r"(addr));
}
__device__ __forceinline__ void mma_bf16(float* d, const uint32_t* a,
                                         uint32_t b0, uint32_t b1) {
    asm volatile("mma.sync.aligned.m16n8k16.row.col.f32.bf16.bf16.f32 "
        "{%0,%1,%2,%3}, {%4,%5,%6,%7}, {%8,%9}, {%0,%1,%2,%3};"
        : "+f"(d[0]), "+f"(d[1]), "+f"(d[2]), "+f"(d[3])
        : "r"(a[0]), "r"(a[1]), "r"(a[2]), "r"(a[3]), "r"(b0), "r"(b1));
}
__device__ __forceinline__ unsigned short bf_bits(__nv_bfloat16 b) {
    return *reinterpret_cast<unsigned short*>(&b);
}
__device__ __forceinline__ uint32_t cvt_bf2(float hi, float lo) {
    uint32_t r;
    asm("cvt.rn.bf16x2.f32 %0, %1, %2;" : "=r"(r) : "f"(hi), "f"(lo));
    return r;
}
__device__ __forceinline__ unsigned long long pack64(uint32_t lo, uint32_t hi) {
    unsigned long long v;
    asm("mov.b64 %0, {%1, %2};" : "=l"(v) : "r"(lo), "r"(hi));
    return v;
}
__device__ __forceinline__ void cpasync16(uint32_t dst, const void* src) {
    asm volatile("cp.async.ca.shared.global [%0], [%1], 16;"
        :: "r"(dst), "l"(src) : "memory");
}
__device__ __forceinline__ void cpasync_commit() {
    asm volatile("cp.async.commit_group;" ::: "memory");
}
__device__ __forceinline__ void cpasync_wait0() {
    asm volatile("cp.async.wait_group 0;" ::: "memory");
}

// ---------------------------------------------------------------------------
// Edge kernel — EXACT R10 winner (189.1 us). h = radial @ w1 on HMMA,
// 3-term bf16 hi/lo split, fp32 acc; cp.async double-buffered raw tiles;
// softplus . w2 epilogue + atomics.
// ---------------------------------------------------------------------------
__global__ __launch_bounds__(256, 2) void edge_kernel(
    const float* __restrict__ nbr_fea,
    const int*   __restrict__ nbr_idx,
    const float* __restrict__ w1,
    const float* __restrict__ b1,
    const float* __restrict__ w2,
    const float* __restrict__ b2)
{
    extern __shared__ char dyn[];
    const uint32_t raw_a = smem_u32(dyn);
    const uint32_t base  = (raw_a + 1023u) & ~1023u;
    char* bp = dyn + (base - raw_a);

    const int tid  = threadIdx.x;
    const int wid  = tid >> 5;
    const int lane = tid & 31;
    const int gid  = lane >> 2;     // row group 0-7
    const int tid4 = lane & 3;      // col group 0-3

    const int tile0   = blockIdx.x * TILES_PER_CTA;
    const int n_tiles = (tile0 + TILES_PER_CTA <= N_TILES_TOTAL)
                        ? TILES_PER_CTA : (N_TILES_TOTAL - tile0);
    if (n_tiles <= 0) return;

    // ---- stage B = w1 row-major [k][j], bf16 hi/lo, swizzled (once/CTA) ----
    #pragma unroll
    for (int it = 0; it < 16; it++) {
        int idx = it * 256 + tid;          // [0, 4096)
        int k = idx >> 6, j = idx & 63;
        float v = w1[idx];
        __nv_bfloat16 bh = __float2bfloat16(v);
        __nv_bfloat16 bl = __float2bfloat16(v - __bfloat162float(bh));
        uint32_t off = SMEM_SWZ((uint32_t)(k * 128 + j * 2));
        sts16(base + OFF_B_HI + off, bf_bits(bh));
        sts16(base + OFF_B_LO + off, bf_bits(bl));
    }
    if (tid < 32) {   // interleaved {b1[2t],b1[2t+1],w2[2t],w2[2t+1]}
        float4 bw;
        bw.x = b1[2 * tid];
        bw.y = b1[2 * tid + 1];
        bw.z = w2[(2 * tid) * SH_DIM];
        bw.w = w2[(2 * tid + 1) * SH_DIM];
        *(float4*)(bp + OFF_BW + tid * 16) = bw;
    }
    const float b2v = b2[0];

    // ---- async-prefetch tile 0 raw fp32 ----
    {
        const float* src = nbr_fea + (size_t)tile0 * TILE_E * NBR_F;
        #pragma unroll
        for (int it = 0; it < 8; it++) {
            int idx = it * 256 + tid;
            cpasync16(base + OFF_RAW + idx * 16, src + idx * 4);
        }
        cpasync_commit();
    }

    for (int t = 0; t < n_tiles; t++) {
        const int tb = (tile0 + t) * TILE_E;

        // hoist idx loads for this tile (consumed at epilogue end)
        int ia0 = 0, ia1 = 0;
        if (tid4 == 0) {
            int r0 = wid * 16 + gid;
            ia0 = nbr_idx[tb + r0];
            ia1 = nbr_idx[tb + r0 + 8];
        }

        cpasync_wait0();
        __syncthreads();   // raw tile ready; prev tile's ldsm reads done

        // ---- convert raw (smem) -> A bf16 hi/lo planes ----
        #pragma unroll
        for (int it = 0; it < 8; it++) {
            int idx = it * 256 + tid;      // [0, 2048) float4 quads
            int row = idx >> 4, q = idx & 15;
            float4 v = *(const float4*)(bp + OFF_RAW + idx * 16);
            uint32_t h01 = cvt_bf2(v.y, v.x);
            uint32_t h23 = cvt_bf2(v.w, v.z);
            float f0 = __uint_as_float(h01 << 16);
            float f1 = __uint_as_float(h01 & 0xffff0000u);
            float f2 = __uint_as_float(h23 << 16);
            float f3 = __uint_as_float(h23 & 0xffff0000u);
            uint32_t l01 = cvt_bf2(v.y - f1, v.x - f0);
            uint32_t l23 = cvt_bf2(v.w - f3, v.z - f2);
            uint32_t off = SMEM_SWZ((uint32_t)(row * 128 + q * 8));
            sts64(base + OFF_A_HI + off, pack64(h01, h23));
            sts64(base + OFF_A_LO + off, pack64(l01, l23));
        }
        __syncthreads();   // A ready; raw buffer free for refill

        // ---- kick off next tile's raw prefetch (overlaps mainloop) ----
        if (t + 1 < n_tiles) {
            const float* src = nbr_fea + (size_t)(tb + TILE_E) * NBR_F;
            #pragma unroll
            for (int it = 0; it < 8; it++) {
                int idx = it * 256 + tid;
                cpasync16(base + OFF_RAW + idx * 16, src + idx * 4);
            }
            cpasync_commit();
        }

        // ---- mainloop ----
        float acc[8][4];
        #pragma unroll
        for (int nt = 0; nt < 8; nt++)
            #pragma unroll
            for (int c = 0; c < 4; c++) acc[nt][c] = 0.0f;

        // Pass 1: (A_hi + A_lo) . B_hi — B fragment loaded once, used twice
        #pragma unroll
        for (int ks = 0; ks < 4; ks++) {
            uint32_t ah[4], al[4];
            uint32_t aoff = (uint32_t)((wid * 16 + (lane & 15)) * 128
                                       + ks * 32 + (lane >> 4) * 16);
            ldsm_x4(base + OFF_A_HI + SMEM_SWZ(aoff), ah);
            ldsm_x4(base + OFF_A_LO + SMEM_SWZ(aoff), al);
            #pragma unroll
            for (int nt = 0; nt < 8; nt++) {
                uint32_t boff = (uint32_t)((ks * 16 + (lane & 15)) * 128 + nt * 16);
                uint32_t b0, b1r;
                ldsm_x2t(base + OFF_B_HI + SMEM_SWZ(boff), b0, b1r);
                mma_bf16(acc[nt], ah, b0, b1r);
                mma_bf16(acc[nt], al, b0, b1r);
            }
        }
        // Pass 2: A_hi . B_lo
        #pragma unroll
        for (int ks = 0; ks < 4; ks++) {
            uint32_t ah[4];
            uint32_t aoff = (uint32_t)((wid * 16 + (lane & 15)) * 128
                                       + ks * 32 + (lane >> 4) * 16);
            ldsm_x4(base + OFF_A_HI + SMEM_SWZ(aoff), ah);
            #pragma unroll
            for (int nt = 0; nt < 8; nt++) {
                uint32_t boff = (uint32_t)((ks * 16 + (lane & 15)) * 128 + nt * 16);
                uint32_t b0, b1r;
                ldsm_x2t(base + OFF_B_LO + SMEM_SWZ(boff), b0, b1r);
                mma_bf16(acc[nt], ah, b0, b1r);
            }
        }

        // ---- epilogue: softplus . w2, quad-reduce, atomics ----
        float s0 = 0.0f, s1 = 0.0f;
        #pragma unroll
        for (int nt = 0; nt < 8; nt++) {
            int colp = nt * 4 + tid4;     // float4 index = col/2
            float4 bw = *(const float4*)(bp + OFF_BW + colp * 16);
            float h0 = acc[nt][0] + bw.x;   // row gid
            float h1 = acc[nt][1] + bw.y;
            float h2 = acc[nt][2] + bw.x;   // row gid+8
            float h3 = acc[nt][3] + bw.y;
            float p0 = fmaxf(h0, 0.0f) + __logf(1.0f + __expf(-fabsf(h0)));
            float p1 = fmaxf(h1, 0.0f) + __logf(1.0f + __expf(-fabsf(h1)));
            float p2 = fmaxf(h2, 0.0f) + __logf(1.0f + __expf(-fabsf(h2)));
            float p3 = fmaxf(h3, 0.0f) + __logf(1.0f + __expf(-fabsf(h3)));
            s0 = fmaf(p0, bw.z, s0); s0 = fmaf(p1, bw.w, s0);
            s1 = fmaf(p2, bw.z, s1); s1 = fmaf(p3, bw.w, s1);
        }
        s0 += __shfl_xor_sync(0xffffffffu, s0, 1);
        s0 += __shfl_xor_sync(0xffffffffu, s0, 2);
        s1 += __shfl_xor_sync(0xffffffffu, s1, 1);
        s1 += __shfl_xor_sync(0xffffffffu, s1, 2);
        if (tid4 == 0) {
            int a0 = ia0;
            a0 = (a0 < 0) ? 0 : (a0 >= N_ATOMS ? N_ATOMS - 1 : a0);
            atomicAdd(&g_S[a0], s0 + b2v);
            atomicAdd(&g_C[a0], 1.0f);
            int a1 = ia1;
            a1 = (a1 < 0) ? 0 : (a1 >= N_ATOMS ? N_ATOMS - 1 : a1);
            atomicAdd(&g_S[a1], s1 + b2v);
            atomicAdd(&g_C[a1], 1.0f);
        }
    }
}

// ---------------------------------------------------------------------------
// Output GEMM on HMMA. 4 atom-tiles (64 atoms) per CTA: tp_w staged ONCE per
// CTA (float4 loads, paired bf16x2 STS.32). Paired x4.trans B loads.
// ---------------------------------------------------------------------------
#define OT_M 64
#define OT_TILES 4
#define N_OUT_CTAS ((N_ATOMS + OT_M * OT_TILES - 1) / (OT_M * OT_TILES))   // 196

#define O_A_HI 0        // 2 kc-planes x 8192 (64 rows x 128B)
#define O_A_LO 16384
#define O_B_HI 32768    // 4 planes [kc][ch] x 8192
#define O_B_LO 65536
#define OUT_SMEM_USED 98304
#define OUT_SMEM_BYTES (OUT_SMEM_USED + 1024)

__global__ __launch_bounds__(256, 2) void out_kernel(
    const float* __restrict__ atom_fea,
    const float* __restrict__ tp_w,
    float* __restrict__ out)
{
    extern __shared__ char dyn[];
    const uint32_t raw_a = smem_u32(dyn);
    const uint32_t base  = (raw_a + 1023u) & ~1023u;

    const int tid  = threadIdx.x;
    const int wid  = tid >> 5;
    const int lane = tid & 31;
    const int gid  = lane >> 2;
    const int tid4 = lane & 3;
    const int mt   = wid & 3;       // m-tile (16 atoms)
    const int ch   = wid >> 2;      // col half (64 cols)

    // ---- stage B = tp_w [k][j] bf16 hi/lo into 4 planes [kc][jh] (once) ----
    // float4 loads (4 consecutive j), bf16x2 pair stores.
    {
        const float4* tw4 = (const float4*)tp_w;
        #pragma unroll
        for (int it = 0; it < 16; it++) {
            int fidx = it * 256 + tid;         // [0, 4096) float4s
            int k = fidx >> 5;                 // 32 float4 per 128-col row
            int jq = fidx & 31;
            int j = jq * 4;                    // j..j+3 same 64-col plane
            float4 v = tw4[fidx];
            uint32_t h01 = cvt_bf2(v.y, v.x);
            uint32_t h23 = cvt_bf2(v.w, v.z);
            float f0 = __uint_as_float(h01 << 16);
            float f1 = __uint_as_float(h01 & 0xffff0000u);
            float f2 = __uint_as_float(h23 << 16);
            float f3 = __uint_as_float(h23 & 0xffff0000u);
            uint32_t l01 = cvt_bf2(v.y - f1, v.x - f0);
            uint32_t l23 = cvt_bf2(v.w - f3, v.z - f2);
            uint32_t plane = (uint32_t)(((k >> 6) * 2 + (j >> 6)) * 8192);
            uint32_t o0 = plane + SMEM_SWZ((uint32_t)((k & 63) * 128 + (j & 63) * 2));
            uint32_t o1 = plane + SMEM_SWZ((uint32_t)((k & 63) * 128 + ((j + 2) & 63) * 2));
            sts32(base + O_B_HI + o0, h01);
            sts32(base + O_B_HI + o1, h23);
            sts32(base + O_B_LO + o0, l01);
            sts32(base + O_B_LO + o1, l23);
        }
    }

    for (int t = 0; t < OT_TILES; t++) {
        const int abase = (blockIdx.x * OT_TILES + t) * OT_M;
        if (abase >= N_ATOMS) break;

        __syncthreads();   // B ready (t==0) / prev tile's A reads done

        // ---- stage A tile (64 atoms x 128 k) bf16 hi/lo, 2 kc planes ----
        #pragma unroll
        for (int it = 0; it < 8; it++) {
            int idx = it * 256 + tid;          // [0, 2048) float4 quads
            int row = idx >> 5, q = idx & 31;
            int kc = q >> 4, qq = q & 15;
            int atom = abase + row;
            float4 v = make_float4(0.f, 0.f, 0.f, 0.f);
            if (atom < N_ATOMS)
                v = *(const float4*)(atom_fea + (size_t)atom * ATOM_F + q * 4);
            uint32_t h01 = cvt_bf2(v.y, v.x);
            uint32_t h23 = cvt_bf2(v.w, v.z);
            float f0 = __uint_as_float(h01 << 16);
            float f1 = __uint_as_float(h01 & 0xffff0000u);
            float f2 = __uint_as_float(h23 << 16);
            float f3 = __uint_as_float(h23 & 0xffff0000u);
            uint32_t l01 = cvt_bf2(v.y - f1, v.x - f0);
            uint32_t l23 = cvt_bf2(v.w - f3, v.z - f2);
            uint32_t off = (uint32_t)(kc * 8192)
                         + SMEM_SWZ((uint32_t)(row * 128 + qq * 8));
            sts64(base + O_A_HI + off, pack64(h01, h23));
            sts64(base + O_A_LO + off, pack64(l01, l23));
        }
        __syncthreads();

        // ---- mainloop: 2 k-chunks x 4 ks, paired-nt B loads ----
        float acc[8][4];
        #pragma unroll
        for (int nt = 0; nt < 8; nt++)
            #pragma unroll
            for (int c = 0; c < 4; c++) acc[nt][c] = 0.0f;

        #pragma unroll
        for (int kc = 0; kc < 2; kc++) {
            const uint32_t apl = (uint32_t)(kc * 8192);
            const uint32_t bpl = (uint32_t)((kc * 2 + ch) * 8192);
            #pragma unroll
            for (int ks = 0; ks < 4; ks++) {
                uint32_t ah[4], al[4];
                uint32_t aoff = apl + SMEM_SWZ((uint32_t)((mt * 16 + (lane & 15)) * 128
                                               + ks * 32 + (lane >> 4) * 16));
                ldsm_x4(base + O_A_HI + aoff, ah);
                ldsm_x4(base + O_A_LO + aoff, al);
                #pragma unroll
                for (int ntp = 0; ntp < 4; ntp++) {
                    uint32_t boff = bpl + SMEM_SWZ((uint32_t)((ks * 16 + (lane & 15)) * 128
                                                   + (ntp * 2 + (lane >> 4)) * 16));
                    uint32_t bh4[4], bl4[4];
                    ldsm_x4t(base + O_B_HI + boff, bh4);
                    ldsm_x4t(base + O_B_LO + boff, bl4);
                    mma_bf16(acc[2 * ntp],     ah, bh4[0], bh4[1]);
                    mma_bf16(acc[2 * ntp],     al, bh4[0], bh4[1]);
                    mma_bf16(acc[2 * ntp],     ah, bl4[0], bl4[1]);
                    mma_bf16(acc[2 * ntp + 1], ah, bh4[2], bh4[3]);
                    mma_bf16(acc[2 * ntp + 1], al, bh4[2], bh4[3]);
                    mma_bf16(acc[2 * ntp + 1], ah, bl4[2], bl4[3]);
                }
            }
        }

        // ---- epilogue: per-atom scale, write float2 pairs ----
        int atomA = abase + mt * 16 + gid;
        int atomB = atomA + 8;
        float scA = 0.0f, scB = 0.0f;
        if (atomA < N_ATOMS)
            scA = g_S[atomA] * INV_SQRT_F / fmaxf(g_C[atomA], 1.0f);
        if (atomB < N_ATOMS)
            scB = g_S[atomB] * INV_SQRT_F / fmaxf(g_C[atomB], 1.0f);

        #pragma unroll
        for (int nt = 0; nt < 8; nt++) {
            int col = ch * 64 + nt * 8 + tid4 * 2;
            if (atomA < N_ATOMS)
                *(float2*)(out + (size_t)atomA * ATOM_F + col) =
                    make_float2(acc[nt][0] * scA, acc[nt][1] * scA);
            if (atomB < N_ATOMS)
                *(float2*)(out + (size_t)atomB * ATOM_F + col) =
                    make_float2(acc[nt][2] * scB, acc[nt][3] * scB);
        }
    }
}

// ---------------------------------------------------------------------------
// Launch
// ---------------------------------------------------------------------------
extern "C" void kernel_launch(void* const* d_in, const int* in_sizes, int n_in,
                              void* d_out, int out_size)
{
    const float* atom_fea = (const float*)d_in[0];
    const float* nbr_fea  = (const float*)d_in[1];
    const int*   nbr_idx  = (const int*)d_in[2];
    const float* w1       = (const float*)d_in[3];
    const float* b1       = (const float*)d_in[4];
    const float* w2       = (const float*)d_in[5];
    const float* b2       = (const float*)d_in[6];
    const float* tp_w     = (const float*)d_in[7];
    float*       out      = (float*)d_out;

    cudaFuncSetAttribute(edge_kernel,
                         cudaFuncAttributeMaxDynamicSharedMemorySize,
                         EDGE_SMEM_BYTES);
    cudaFuncSetAttribute(out_kernel,
                         cudaFuncAttributeMaxDynamicSharedMemorySize,
                         OUT_SMEM_BYTES);

    zero_kernel<<<(N_ATOMS + 255) / 256, 256>>>();
    edge_kernel<<<N_EDGE_CTAS, 256, EDGE_SMEM_BYTES>>>(nbr_fea, nbr_idx,
                                                       w1, b1, w2, b2);
    out_kernel<<<N_OUT_CTAS, 256, OUT_SMEM_BYTES>>>(atom_fea, tp_w, out);
}